// round 6
// baseline (speedup 1.0000x reference)
#include <cuda_runtime.h>
#include <math_constants.h>

#define B 64
#define T 2048
#define EMB 512
#define ATT 128
#define NF 32
#define KW 31
#define PADW 15
#define TB 64

__device__ float g_q[B * ATT];
__device__ float g_sum[B];
__device__ float g_wlocT[NF * ATT];
__device__ float2 g_wconv2[KW * NF];

typedef unsigned long long u64;
typedef unsigned int u32;

__device__ __forceinline__ u64 pack2(float lo, float hi) {
    u64 r; asm("mov.b64 %0, {%1, %2};" : "=l"(r) : "f"(lo), "f"(hi)); return r;
}
__device__ __forceinline__ void unpack2(u64 v, float& lo, float& hi) {
    asm("mov.b64 {%0, %1}, %2;" : "=f"(lo), "=f"(hi) : "l"(v));
}
__device__ __forceinline__ u64 add2(u64 a, u64 b) {
    u64 r; asm("add.rn.f32x2 %0, %1, %2;" : "=l"(r) : "l"(a), "l"(b)); return r;
}
__device__ __forceinline__ void fma2(u64& d, u64 a, u64 b) {
    asm("fma.rn.f32x2 %0, %1, %2, %0;" : "+l"(d) : "l"(a), "l"(b));
}
__device__ __forceinline__ float tanh_apx(float x) {
    float r; asm("tanh.approx.f32 %0, %1;" : "=f"(r) : "f"(x)); return r;
}
__device__ __forceinline__ u64 lds_u64(const void* p) {
    u64 r;
    asm("ld.shared.u64 %0, [%1];" : "=l"(r)
        : "r"((u32)__cvta_generic_to_shared(p)));
    return r;
}

// ---------------------------------------------------------------------------
// Kernel 1: q = hidden @ W_dec^T. grid (B, 16), 256 thr, one row per warp.
// ---------------------------------------------------------------------------
__global__ void __launch_bounds__(256)
prep_kernel(const float* __restrict__ HID,
            const float* __restrict__ WDEC,
            const float* __restrict__ WLOC,
            const float* __restrict__ WCONV,
            float* __restrict__ OUT_CTX) {
    const int b = blockIdx.x;
    const int chunk = blockIdx.y;            // 8 rows per chunk
    const int tid = threadIdx.x;
    const int w = tid >> 5, lane = tid & 31;

    if (chunk == 0) {
        OUT_CTX[b * EMB + tid] = 0.f;
        OUT_CTX[b * EMB + 256 + tid] = 0.f;
        if (tid == 0) g_sum[b] = 0.f;
    }
    if (b == 0 && chunk == 1) {
        for (int idx = tid; idx < NF * ATT; idx += 256) {
            int a = idx >> 5, c = idx & 31;
            g_wlocT[c * ATT + a] = WLOC[idx];
        }
        for (int idx = tid; idx < KW * NF; idx += 256) {
            int c = idx & 31, k = idx >> 5;
            g_wconv2[k * NF + c] = make_float2(WCONV[(c * 2 + 0) * KW + k],
                                               WCONV[(c * 2 + 1) * KW + k]);
        }
    }

    const int a = chunk * 8 + w;
    const float4* __restrict__ H4 = (const float4*)(HID + b * 1024);
    const float4* __restrict__ WD4 = (const float4*)WDEC + a * 256;

    float acc = 0.f;
    #pragma unroll
    for (int j = 0; j < 8; j++) {
        float4 h = H4[j * 32 + lane];
        float4 v = WD4[j * 32 + lane];
        acc += h.x * v.x + h.y * v.y + h.z * v.z + h.w * v.w;
    }
    #pragma unroll
    for (int s = 16; s; s >>= 1)
        acc += __shfl_xor_sync(0xffffffffu, acc, s);
    if (lane == 0) g_q[b * ATT + a] = acc;
}

// ---------------------------------------------------------------------------
// Kernel 2: w'[b,t] = exp(We . tanh(q + proj(conv(cum)) + MA)); masked -> 0.
// Stage 2 compacts unmasked t via __fns (skips ~50% of projection work).
// grid (T/TB, B), block 128; warp owns 16 consecutive t.
// ---------------------------------------------------------------------------
__global__ void __launch_bounds__(128)
energies_kernel(const float* __restrict__ MA,
                const float* __restrict__ CUM,
                const int* __restrict__ MASK,
                const float* __restrict__ WE,
                float* __restrict__ WOUT) {
    __shared__ float s_wloc[NF][ATT];
    __shared__ u64   s_locd[NF][TB + 2];
    __shared__ alignas(16) float2 s_cum2[TB + 2 * PADW + 2];

    const int b = blockIdx.y;
    const int t0 = blockIdx.x * TB;
    const int tid = threadIdx.x;
    const int w = tid >> 5, lane = tid & 31;

    {
        const float4* __restrict__ src = (const float4*)g_wlocT;
        float4* dst = (float4*)s_wloc;
        #pragma unroll
        for (int j = 0; j < 8; j++) dst[tid + j * 128] = src[tid + j * 128];
    }
    for (int j = tid; j < TB + 2 * PADW + 2; j += 128) {
        int tg = t0 + j - PADW;
        float a0 = 0.f, a1 = 0.f;
        if (tg >= 0 && tg < T) {
            a0 = CUM[(b * 2 + 0) * T + tg];
            a1 = CUM[(b * 2 + 1) * T + tg];
        }
        s_cum2[j] = make_float2(a0, a1);
    }
    __syncthreads();

    const int tl = w * 16;

    // --- stage 1: conv1d, lane = channel, t in pairs (16B broadcasts)
    {
        u64 wk[KW];
        #pragma unroll
        for (int k = 0; k < KW; k++) {
            float2 wv = __ldg(&g_wconv2[k * NF + lane]);
            wk[k] = pack2(wv.x, wv.y);
        }
        #pragma unroll 2
        for (int u = 0; u < 8; u++) {
            const int tp = tl + 2 * u;
            u64 a0 = 0ull, a1 = 0ull;
            #pragma unroll
            for (int m = 0; m < 16; m++) {
                float4 F = *(const float4*)&s_cum2[tp + 2 * m];
                u64 flo = pack2(F.x, F.y);
                u64 fhi = pack2(F.z, F.w);
                fma2(a0, wk[2 * m], flo);
                if (2 * m + 1 < KW) fma2(a0, wk[2 * m + 1], fhi);
                if (m > 0) fma2(a1, wk[2 * m - 1], flo);
                fma2(a1, wk[2 * m], fhi);
            }
            float l0, h0, l1, h1;
            unpack2(a0, l0, h0);
            unpack2(a1, l1, h1);
            float v0 = l0 + h0, v1 = l1 + h1;
            s_locd[lane][tp]     = pack2(v0, v0);
            s_locd[lane][tp + 1] = pack2(v1, v1);
        }
    }
    __syncthreads();

    // --- stage 2: compacted projection over unmasked t only.
    const float4 q4 = *((const float4*)(g_q + b * ATT) + lane);
    const float4 we4 = ((const float4*)WE)[lane];
    const u64 q01 = pack2(q4.x, q4.y);
    const u64 q23 = pack2(q4.z, q4.w);
    const float4* __restrict__ MA4 = (const float4*)MA;

    int mv = 0;
    if (lane < 16) mv = MASK[b * T + t0 + tl + lane];
    const unsigned um = (~__ballot_sync(0xffffffffu, mv != 0)) & 0xffffu;
    const int n = __popc(um);   // number of unmasked t in this warp's 16

    float myw = 0.f;   // lane j (<16) holds weight for t = t0+tl+j
    float psum = 0.f;

    for (int base = 0; base < n; base += 8) {
        int tj[8];
        bool valid[8];
        #pragma unroll
        for (int j = 0; j < 8; j++) {
            const int pos = base + j;
            valid[j] = (pos < n);
            unsigned f = __fns(um, 0, pos + 1);   // pos-th set bit
            tj[j] = valid[j] ? (int)f : 0;
        }

        u64 v01[8], v23[8];
        #pragma unroll
        for (int j = 0; j < 8; j++) {
            float4 m = MA4[((size_t)b * T + t0 + tl + tj[j]) * (ATT / 4) + lane];
            v01[j] = add2(q01, pack2(m.x, m.y));
            v23[j] = add2(q23, pack2(m.z, m.w));
        }
        #pragma unroll 4
        for (int c = 0; c < NF; c++) {
            float4 wf = ((const float4*)s_wloc[c])[lane];  // LDS.128 lane-distinct
            u64 w01 = pack2(wf.x, wf.y);
            u64 w23 = pack2(wf.z, wf.w);
            #pragma unroll
            for (int j = 0; j < 8; j++) {
                u64 lc = lds_u64(&s_locd[c][tl + tj[j]]);  // 8B broadcast
                fma2(v01[j], lc, w01);
                fma2(v23[j], lc, w23);
            }
        }
        #pragma unroll
        for (int j = 0; j < 8; j++) {
            if (valid[j]) {
                float a0, a1, a2, a3;
                unpack2(v01[j], a0, a1);
                unpack2(v23[j], a2, a3);
                float e = we4.x * tanh_apx(a0) + we4.y * tanh_apx(a1)
                        + we4.z * tanh_apx(a2) + we4.w * tanh_apx(a3);
                #pragma unroll
                for (int s = 16; s; s >>= 1)
                    e += __shfl_xor_sync(0xffffffffu, e, s);
                float wexp = __expf(e);   // |e| small: no max subtraction
                if (lane == tj[j]) myw = wexp;
                psum += wexp;
            }
        }
    }
    if (lane < 16) WOUT[b * T + t0 + tl + lane] = myw;   // masked lanes write 0
    if (lane == 0 && n > 0) atomicAdd(&g_sum[b], psum);
}

// ---------------------------------------------------------------------------
// Kernel 3: normalize weights in place + context accumulation (mask-skip)
// ---------------------------------------------------------------------------
__global__ void context_kernel(const float* __restrict__ MEM,
                               float* __restrict__ WROW,
                               float* __restrict__ CTX) {
    const int TSEG = 128;
    const int b = blockIdx.y;
    const int tbase = blockIdx.x * TSEG;
    const int tid = threadIdx.x;

    __shared__ float s_w[TSEG];
    s_w[tid] = WROW[b * T + tbase + tid];
    __syncthreads();

    const float inv = 1.f / g_sum[b];
    WROW[b * T + tbase + tid] = s_w[tid] * inv;

    const float4* __restrict__ M4 =
        (const float4*)MEM + ((size_t)b * T + tbase) * (EMB / 4);
    float4 acc = make_float4(0.f, 0.f, 0.f, 0.f);
    #pragma unroll 8
    for (int t = 0; t < TSEG; t++) {
        float wt = s_w[t];
        if (wt != 0.f) {   // warp-uniform skip of masked rows
            float4 m = __ldcs(&M4[(size_t)t * (EMB / 4) + tid]);
            acc.x += wt * m.x;
            acc.y += wt * m.y;
            acc.z += wt * m.z;
            acc.w += wt * m.w;
        }
    }
    float* dst = CTX + b * EMB + tid * 4;
    atomicAdd(dst + 0, acc.x * inv);
    atomicAdd(dst + 1, acc.y * inv);
    atomicAdd(dst + 2, acc.z * inv);
    atomicAdd(dst + 3, acc.w * inv);
}

// ---------------------------------------------------------------------------
extern "C" void kernel_launch(void* const* d_in, const int* in_sizes, int n_in,
                              void* d_out, int out_size) {
    const float* hid   = (const float*)d_in[0];
    const float* mem   = (const float*)d_in[1];
    const float* ma    = (const float*)d_in[2];
    const float* cum   = (const float*)d_in[3];
    const int*   mask  = (const int*)d_in[4];
    const float* wdec  = (const float*)d_in[5];
    const float* wconv = (const float*)d_in[6];
    const float* wloc  = (const float*)d_in[7];
    const float* we    = (const float*)d_in[8];

    float* out_ctx = (float*)d_out;
    float* out_w   = (float*)d_out + B * EMB;

    dim3 gp(B, 16);
    prep_kernel<<<gp, 256>>>(hid, wdec, wloc, wconv, out_ctx);
    dim3 ge(T / TB, B);
    energies_kernel<<<ge, 128>>>(ma, cum, mask, we, out_w);
    dim3 gc(16, B);
    context_kernel<<<gc, 128>>>(mem, out_w, out_ctx);
}

// round 7
// speedup vs baseline: 1.0497x; 1.0497x over previous
#include <cuda_runtime.h>
#include <math_constants.h>

#define B 64
#define T 2048
#define EMB 512
#define ATT 128
#define NF 32
#define KW 31
#define PADW 15
#define TB 64
#define KT 8          // k-split tiles in prep gemm

__device__ float g_qp[KT * B * ATT];   // q partials per k-tile
__device__ float g_sum[B];
__device__ float g_wlocT[NF * ATT];
__device__ float2 g_wconv2[KW * NF];

typedef unsigned long long u64;
typedef unsigned int u32;

__device__ __forceinline__ u64 pack2(float lo, float hi) {
    u64 r; asm("mov.b64 %0, {%1, %2};" : "=l"(r) : "f"(lo), "f"(hi)); return r;
}
__device__ __forceinline__ void unpack2(u64 v, float& lo, float& hi) {
    asm("mov.b64 {%0, %1}, %2;" : "=f"(lo), "=f"(hi) : "l"(v));
}
__device__ __forceinline__ u64 add2(u64 a, u64 b) {
    u64 r; asm("add.rn.f32x2 %0, %1, %2;" : "=l"(r) : "l"(a), "l"(b)); return r;
}
__device__ __forceinline__ void fma2(u64& d, u64 a, u64 b) {
    asm("fma.rn.f32x2 %0, %1, %2, %0;" : "+l"(d) : "l"(a), "l"(b));
}
__device__ __forceinline__ float tanh_apx(float x) {
    float r; asm("tanh.approx.f32 %0, %1;" : "=f"(r) : "f"(x)); return r;
}

// ---------------------------------------------------------------------------
// Kernel 1: split-K GEMM q = hidden @ W_dec^T  -> g_qp partials, plus
// housekeeping in block 128 (zero ctx/g_sum, transpose W_loc / W_conv).
// grid 129 blocks x 256 thr. Block bi<128: atile = bi>>3, ktile = bi&7.
// ---------------------------------------------------------------------------
__global__ void __launch_bounds__(256)
prep_kernel(const float* __restrict__ HID,
            const float* __restrict__ WDEC,
            const float* __restrict__ WLOC,
            const float* __restrict__ WCONV,
            float* __restrict__ OUT_CTX) {
    const int bi = blockIdx.x;
    const int tid = threadIdx.x;

    if (bi == 128) {   // housekeeping block
        float4 z4 = make_float4(0.f, 0.f, 0.f, 0.f);
        float4* c4 = (float4*)OUT_CTX;
        #pragma unroll
        for (int j = 0; j < 32; j++) c4[tid + j * 256] = z4;
        if (tid < B) g_sum[tid] = 0.f;
        for (int idx = tid; idx < NF * ATT; idx += 256) {
            int a = idx >> 5, c = idx & 31;
            g_wlocT[c * ATT + a] = WLOC[idx];
        }
        for (int idx = tid; idx < KW * NF; idx += 256) {
            int c = idx & 31, k = idx >> 5;
            g_wconv2[k * NF + c] = make_float2(WCONV[(c * 2 + 0) * KW + k],
                                               WCONV[(c * 2 + 1) * KW + k]);
        }
        return;
    }

    const int atile = bi >> 3;      // 0..15, rows a = atile*8 .. +8
    const int ktile = bi & 7;       // 0..7,  k  = ktile*128 .. +128
    const int w = tid >> 5, lane = tid & 31;

    __shared__ float4 sh_h[B * 32];   // hidden tile [b][k/4]  (32KB)
    __shared__ float4 sh_w[8 * 32];   // wdec tile   [a][k/4]  (4KB)

    const float4* __restrict__ H4 = (const float4*)HID;
    const float4* __restrict__ WD4 = (const float4*)WDEC;
    // fill hidden tile: warp covers one b (coalesced 512B)
    for (int i = tid; i < B * 32; i += 256) {
        int b = i >> 5, kq = i & 31;
        sh_h[i] = H4[b * 256 + ktile * 32 + kq];
    }
    if (tid < 8 * 32) {
        int a = tid >> 5, kq = tid & 31;
        sh_w[tid] = WD4[(atile * 8 + a) * 256 + ktile * 32 + kq];
    }
    __syncthreads();

    // warp w: 4 passes of 2 b; lanes split k (each lane owns 4 consecutive k)
    #pragma unroll
    for (int p = 0; p < 4; p++) {
        const int b0 = w * 8 + p * 2;
        float4 h0 = sh_h[b0 * 32 + lane];
        float4 h1 = sh_h[(b0 + 1) * 32 + lane];
        float r[16];
        #pragma unroll
        for (int a = 0; a < 8; a++) {
            float4 wd = sh_w[a * 32 + lane];
            r[a]     = h0.x * wd.x + h0.y * wd.y + h0.z * wd.z + h0.w * wd.w;
            r[8 + a] = h1.x * wd.x + h1.y * wd.y + h1.z * wd.z + h1.w * wd.w;
        }
        #pragma unroll
        for (int s = 16; s; s >>= 1) {
            #pragma unroll
            for (int i = 0; i < 16; i++)
                r[i] += __shfl_xor_sync(0xffffffffu, r[i], s);
        }
        if (lane == 0) {
            float* dst = g_qp + (ktile * B) * ATT + atile * 8;
            #pragma unroll
            for (int a = 0; a < 8; a++) {
                dst[b0 * ATT + a] = r[a];
                dst[(b0 + 1) * ATT + a] = r[8 + a];
            }
        }
    }
}

// ---------------------------------------------------------------------------
// Kernel 2: w'[b,t] = exp(We . tanh(q + proj(conv(cum)) + MA)); masked -> 0.
// grid (T/TB, B), block 128; warp owns 16 consecutive t (single pass).
// ---------------------------------------------------------------------------
__global__ void __launch_bounds__(128)
energies_kernel(const float* __restrict__ MA,
                const float* __restrict__ CUM,
                const int* __restrict__ MASK,
                const float* __restrict__ WE,
                float* __restrict__ WOUT) {
    __shared__ float s_wloc[NF][ATT];
    __shared__ u64   s_locd[NF][TB + 2];
    __shared__ alignas(16) float2 s_cum2[TB + 2 * PADW + 2];

    const int b = blockIdx.y;
    const int t0 = blockIdx.x * TB;
    const int tid = threadIdx.x;
    const int w = tid >> 5, lane = tid & 31;

    {
        const float4* __restrict__ src = (const float4*)g_wlocT;
        float4* dst = (float4*)s_wloc;
        #pragma unroll
        for (int j = 0; j < 8; j++) dst[tid + j * 128] = src[tid + j * 128];
    }
    for (int j = tid; j < TB + 2 * PADW + 2; j += 128) {
        int tg = t0 + j - PADW;
        float a0 = 0.f, a1 = 0.f;
        if (tg >= 0 && tg < T) {
            a0 = CUM[(b * 2 + 0) * T + tg];
            a1 = CUM[(b * 2 + 1) * T + tg];
        }
        s_cum2[j] = make_float2(a0, a1);
    }
    __syncthreads();

    const int tl = w * 16;

    // --- stage 1: conv1d, lane = channel, t in pairs (16B broadcasts)
    {
        u64 wk[KW];
        #pragma unroll
        for (int k = 0; k < KW; k++) {
            float2 wv = __ldg(&g_wconv2[k * NF + lane]);
            wk[k] = pack2(wv.x, wv.y);
        }
        #pragma unroll 2
        for (int u = 0; u < 8; u++) {
            const int tp = tl + 2 * u;
            u64 a0 = 0ull, a1 = 0ull;
            #pragma unroll
            for (int m = 0; m < 16; m++) {
                float4 F = *(const float4*)&s_cum2[tp + 2 * m];
                u64 flo = pack2(F.x, F.y);
                u64 fhi = pack2(F.z, F.w);
                fma2(a0, wk[2 * m], flo);
                if (2 * m + 1 < KW) fma2(a0, wk[2 * m + 1], fhi);
                if (m > 0) fma2(a1, wk[2 * m - 1], flo);
                fma2(a1, wk[2 * m], fhi);
            }
            float l0, h0, l1, h1;
            unpack2(a0, l0, h0);
            unpack2(a1, l1, h1);
            float v0 = l0 + h0, v1 = l1 + h1;
            s_locd[lane][tp]     = pack2(v0, v0);
            s_locd[lane][tp + 1] = pack2(v1, v1);
        }
    }
    __syncthreads();

    // --- q: sum the 8 k-tile partials (L2-hot)
    const float4* __restrict__ QP4 = (const float4*)g_qp;
    float4 q4 = QP4[((size_t)b * ATT) / 4 + lane];
    #pragma unroll
    for (int kt = 1; kt < KT; kt++) {
        float4 p = QP4[((size_t)(kt * B + b) * ATT) / 4 + lane];
        q4.x += p.x; q4.y += p.y; q4.z += p.z; q4.w += p.w;
    }
    const float4 we4 = ((const float4*)WE)[lane];
    const u64 q01 = pack2(q4.x, q4.y);
    const u64 q23 = pack2(q4.z, q4.w);
    const float4* __restrict__ MA4 = (const float4*)MA;

    // --- stage 2: 16-t register-blocked projection
    int mv = 0;
    if (lane < 16) mv = MASK[b * T + t0 + tl + lane];
    const unsigned mb = __ballot_sync(0xffffffffu, mv != 0) & 0xffffu;

    u64 v01[16], v23[16];
    #pragma unroll
    for (int j = 0; j < 16; j++) {
        if (!((mb >> j) & 1u)) {
            const int t = t0 + tl + j;
            float4 m = MA4[((size_t)b * T + t) * (ATT / 4) + lane];
            v01[j] = add2(q01, pack2(m.x, m.y));
            v23[j] = add2(q23, pack2(m.z, m.w));
        } else {
            v01[j] = q01; v23[j] = q23;
        }
    }
    #pragma unroll 4
    for (int c = 0; c < NF; c++) {
        float4 wf = ((const float4*)s_wloc[c])[lane];   // LDS.128 lane-distinct
        u64 w01 = pack2(wf.x, wf.y);
        u64 w23 = pack2(wf.z, wf.w);
        #pragma unroll
        for (int r = 0; r < 8; r++) {
            ulonglong2 L = *(const ulonglong2*)&s_locd[c][tl + 2 * r];  // 16B bcast
            fma2(v01[2 * r],     L.x, w01);
            fma2(v23[2 * r],     L.x, w23);
            fma2(v01[2 * r + 1], L.y, w01);
            fma2(v23[2 * r + 1], L.y, w23);
        }
    }

    float myw = 0.f;   // lane j (<16) holds weight for t = t0+tl+j
    float psum = 0.f;
    #pragma unroll
    for (int j = 0; j < 16; j++) {
        if (!((mb >> j) & 1u)) {
            float a0, a1, a2, a3;
            unpack2(v01[j], a0, a1);
            unpack2(v23[j], a2, a3);
            float e = we4.x * tanh_apx(a0) + we4.y * tanh_apx(a1)
                    + we4.z * tanh_apx(a2) + we4.w * tanh_apx(a3);
            #pragma unroll
            for (int s = 16; s; s >>= 1)
                e += __shfl_xor_sync(0xffffffffu, e, s);
            float wexp = __expf(e);   // |e| small: no max subtraction needed
            if (lane == j) myw = wexp;
            psum += wexp;
        }
    }
    if (lane < 16) WOUT[b * T + t0 + tl + lane] = myw;   // masked lanes write 0
    if (lane == 0 && mb != 0xffffu) atomicAdd(&g_sum[b], psum);
}

// ---------------------------------------------------------------------------
// Kernel 3: normalize weights in place + context accumulation (mask-skip)
// ---------------------------------------------------------------------------
__global__ void context_kernel(const float* __restrict__ MEM,
                               float* __restrict__ WROW,
                               float* __restrict__ CTX) {
    const int TSEG = 128;
    const int b = blockIdx.y;
    const int tbase = blockIdx.x * TSEG;
    const int tid = threadIdx.x;

    __shared__ float s_w[TSEG];
    s_w[tid] = WROW[b * T + tbase + tid];
    __syncthreads();

    const float inv = 1.f / g_sum[b];
    WROW[b * T + tbase + tid] = s_w[tid] * inv;

    const float4* __restrict__ M4 =
        (const float4*)MEM + ((size_t)b * T + tbase) * (EMB / 4);
    float4 acc = make_float4(0.f, 0.f, 0.f, 0.f);
    #pragma unroll 8
    for (int t = 0; t < TSEG; t++) {
        float wt = s_w[t];
        if (wt != 0.f) {   // warp-uniform skip of masked rows
            float4 m = __ldcs(&M4[(size_t)t * (EMB / 4) + tid]);
            acc.x += wt * m.x;
            acc.y += wt * m.y;
            acc.z += wt * m.z;
            acc.w += wt * m.w;
        }
    }
    float* dst = CTX + b * EMB + tid * 4;
    atomicAdd(dst + 0, acc.x * inv);
    atomicAdd(dst + 1, acc.y * inv);
    atomicAdd(dst + 2, acc.z * inv);
    atomicAdd(dst + 3, acc.w * inv);
}

// ---------------------------------------------------------------------------
extern "C" void kernel_launch(void* const* d_in, const int* in_sizes, int n_in,
                              void* d_out, int out_size) {
    const float* hid   = (const float*)d_in[0];
    const float* mem   = (const float*)d_in[1];
    const float* ma    = (const float*)d_in[2];
    const float* cum   = (const float*)d_in[3];
    const int*   mask  = (const int*)d_in[4];
    const float* wdec  = (const float*)d_in[5];
    const float* wconv = (const float*)d_in[6];
    const float* wloc  = (const float*)d_in[7];
    const float* we    = (const float*)d_in[8];

    float* out_ctx = (float*)d_out;
    float* out_w   = (float*)d_out + B * EMB;

    prep_kernel<<<129, 256>>>(hid, wdec, wloc, wconv, out_ctx);
    dim3 ge(T / TB, B);
    energies_kernel<<<ge, 128>>>(ma, cum, mask, we, out_w);
    dim3 gc(16, B);
    context_kernel<<<gc, 128>>>(mem, out_w, out_ctx);
}